// round 9
// baseline (speedup 1.0000x reference)
#include <cuda_runtime.h>
#include <cstdint>

// MeanConv: out = (1/7) * sum_{k in {3,5,7,9,11,13,15}} box_mean_k(x, replicate pad) * mask
//
// R8: saturate the smem crossbar.
//  - cp.async raw-row loads (no prefetch registers) -> regs fit 5 CTAs/SM
//  - __launch_bounds__(256,5); SH=32 -> grid 2048 (2.8 waves, small tail)
//  - one __syncthreads per 8-row chunk; per-warp row ownership for load+scan
//  - 32-slot ring of horizontal prefix rows; per-thread 7 vertical running sums

#define H_DIM 4096
#define W_DIM 4096
#define TW    256
#define NTH   256
#define SH    32
#define HALO  7
#define NROWVALS (TW + 2*HALO)     // 270
#define TWP      272               // padded smem row stride (floats)
#define RING     32
#define CHUNK    8                 // rows per chunk == warps per block
#define NCHUNK   (SH / CHUNK)      // 4

__device__ __forceinline__ int clampi(int v, int lo, int hi) { return min(max(v, lo), hi); }

__global__ __launch_bounds__(NTH, 5)
void meanconv_kernel(const float* __restrict__ x,
                     const float* __restrict__ mask,
                     float* __restrict__ out)
{
    __shared__ float ring[RING][TWP];

    const int t    = threadIdx.x;
    const int lane = t & 31;
    const int wrp  = t >> 5;
    const int c0   = blockIdx.x * TW;
    const int r0   = blockIdx.y * SH;
    const int j    = t + HALO;     // this thread's center position in a prefix row

    const uint32_t ring_u32 = (uint32_t)__cvta_generic_to_shared(ring);

    // ---- warp w: async-copy raw row (base_row + w), clamped, into its ring slot ----
    auto issue_row = [&](int base_row) {
        const int gr  = base_row + wrp;
        const int grc = clampi(gr, 0, H_DIM - 1);
        const float* __restrict__ rowp = x + (size_t)grc * W_DIM;
        const uint32_t s = ring_u32 + (uint32_t)((gr & (RING - 1)) * TWP * 4);
        #pragma unroll
        for (int i = 0; i < 9; i++) {
            const int col = lane + 32 * i;
            if (col < NROWVALS) {
                const int gc = clampi(c0 - HALO + col, 0, W_DIM - 1);
                asm volatile("cp.async.ca.shared.global [%0], [%1], 4;"
                             :: "r"(s + (uint32_t)col * 4), "l"(rowp + gc));
            }
        }
        asm volatile("cp.async.commit_group;");
    };

    // ---- warp w: in-place prefix scan of its row -> P[0..270] ----
    auto scan_row = [&](int base_row) {
        float* __restrict__ row = ring[(base_row + wrp) & (RING - 1)];
        const int base = lane * 9;                 // lanes 0..29 cover 0..269
        float ps[9];
        float tot = 0.0f;
        if (base < NROWVALS) {
            float s = row[base];
            ps[0] = s;
            #pragma unroll
            for (int i = 1; i < 9; i++) { s += row[base + i]; ps[i] = s; }
            tot = s;
        }
        float inc = tot;
        #pragma unroll
        for (int d = 1; d < 32; d <<= 1) {
            float n = __shfl_up_sync(0xffffffffu, inc, d);
            if (lane >= d) inc += n;
        }
        const float excl = inc - tot;
        __syncwarp();                              // raw reads done before overwrite
        if (lane == 0) row[0] = 0.0f;
        if (base < NROWVALS) {
            #pragma unroll
            for (int i = 0; i < 9; i++) row[base + i + 1] = excl + ps[i];
        }
    };

    // ---- preload: rows r0-8..r0+7 (two chunks) + async-prefetch r0+8..r0+15 ----
    issue_row(r0 - 8);
    issue_row(r0);
    issue_row(r0 + 8);
    asm volatile("cp.async.wait_group 1;");        // first two groups landed
    __syncwarp();
    scan_row(r0 - 8);
    scan_row(r0);
    __syncthreads();

    // ---- init vertical running sums: acc[ki] covers rows [r0-hk, r0+hk] ----
    float acc[7];
    #pragma unroll
    for (int ki = 0; ki < 7; ki++) {
        const int hk = ki + 1;                     // k = 2*hk+1
        float a = 0.0f;
        #pragma unroll
        for (int d = -7; d <= 7; d++) {
            if (d < -hk || d > hk) continue;
            const float* __restrict__ rp = &ring[(r0 + d) & (RING - 1)][j];
            a += rp[hk + 1] - rp[-hk];
        }
        acc[ki] = a;
    }

    // ---- main sweep: 1 barrier per chunk; cp.async overlaps the consume ----
    for (int c = 0; c < NCHUNK; c++) {
        const int prow = r0 + 8 + c * CHUNK;       // rows produced this chunk
        asm volatile("cp.async.wait_group 0;");    // G(prow) complete
        __syncwarp();
        scan_row(prow);
        __syncthreads();                           // scanned rows visible; prior
                                                   // chunk's reads all retired
        if (c + 1 < NCHUNK)
            issue_row(prow + CHUNK);               // hides under consume

        const int crow = r0 + c * CHUNK;
        size_t idx = (size_t)crow * W_DIM + (size_t)(c0 + t);

        #pragma unroll
        for (int rr = 0; rr < CHUNK; rr++) {
            const int r = crow + rr;

            float s = acc[0] * (1.0f / (7.0f *   9.0f));
            s = fmaf(acc[1], 1.0f / (7.0f *  25.0f), s);
            s = fmaf(acc[2], 1.0f / (7.0f *  49.0f), s);
            s = fmaf(acc[3], 1.0f / (7.0f *  81.0f), s);
            s = fmaf(acc[4], 1.0f / (7.0f * 121.0f), s);
            s = fmaf(acc[5], 1.0f / (7.0f * 169.0f), s);
            s = fmaf(acc[6], 1.0f / (7.0f * 225.0f), s);
            __stcs(&out[idx], s * __ldcs(&mask[idx]));

            #pragma unroll
            for (int ki = 0; ki < 7; ki++) {
                const int hk = ki + 1;
                const float* __restrict__ ra = &ring[(r + 1 + hk) & (RING - 1)][j];
                const float* __restrict__ rs = &ring[(r - hk)     & (RING - 1)][j];
                acc[ki] += (ra[hk + 1] - ra[-hk]) - (rs[hk + 1] - rs[-hk]);
            }
            idx += W_DIM;
        }
        // no trailing barrier: the cp.async writes issued next chunk target ring
        // slots >= 9 rows below any window this chunk still reads, and the
        // per-chunk __syncthreads orders all prior reads before those writes.
    }
}

extern "C" void kernel_launch(void* const* d_in, const int* in_sizes, int n_in,
                              void* d_out, int out_size)
{
    const float* x    = (const float*)d_in[0];
    const float* mask = (const float*)d_in[1];
    float* out        = (float*)d_out;

    dim3 grid(W_DIM / TW, H_DIM / SH);
    dim3 block(NTH);
    meanconv_kernel<<<grid, block>>>(x, mask, out);
}

// round 10
// speedup vs baseline: 1.1165x; 1.1165x over previous
#include <cuda_runtime.h>
#include <cstdint>

// MeanConv: out = (1/7) * sum_{k in {3,5,7,9,11,13,15}} box_mean_k(x, replicate pad) * mask
//
// R9: R7 geometry (SH=64, TW=256, NTH=256, CHUNK=8) + TMA bulk-copy production.
//  - cp.async.bulk (1 instr / 1088B row) gmem->smem + mbarrier completion:
//    near-zero issue cost and no prefetch registers -> 5 CTAs/SM (40 warps).
//  - aligned 272-float raw window per row; border block-columns fix up the
//    replicate padding in smem (uniform branch, 2/16 block-cols).
//  - 32-slot ring of horizontal prefix rows; per-thread 7 vertical running sums.

#define H_DIM 4096
#define W_DIM 4096
#define TW    256
#define NTH   256
#define SH    64
#define WIN   272                  // raw floats per row window (16B-aligned span)
#define TWP   276                  // padded smem row stride (fits prefix 0..272)
#define RING  32
#define CHUNK 8
#define NCHUNK (SH / CHUNK)        // 8
#define ROW_BYTES (WIN * 4)        // 1088

__device__ __forceinline__ int clampi(int v, int lo, int hi) { return min(max(v, lo), hi); }

__device__ __forceinline__ void mbar_wait(uint32_t mbar, uint32_t parity)
{
    uint32_t done;
    asm volatile(
        "{\n\t.reg .pred p;\n\t"
        "mbarrier.try_wait.parity.acquire.cta.shared::cta.b64 p, [%1], %2;\n\t"
        "selp.b32 %0, 1, 0, p;\n\t}"
        : "=r"(done) : "r"(mbar), "r"(parity) : "memory");
    while (!done) {
        asm volatile(
            "{\n\t.reg .pred p;\n\t"
            "mbarrier.try_wait.parity.acquire.cta.shared::cta.b64 p, [%1], %2, 0x989680;\n\t"
            "selp.b32 %0, 1, 0, p;\n\t}"
            : "=r"(done) : "r"(mbar), "r"(parity) : "memory");
    }
}

__global__ __launch_bounds__(NTH, 5)
void meanconv_kernel(const float* __restrict__ x,
                     const float* __restrict__ mask,
                     float* __restrict__ out)
{
    __shared__ __align__(16) float ring[RING][TWP];
    __shared__ __align__(8) unsigned long long mbar_sto;

    const int t    = threadIdx.x;
    const int lane = t & 31;
    const int wrp  = t >> 5;
    const int c0   = blockIdx.x * TW;
    const int r0   = blockIdx.y * SH;
    const int j    = t + 8;        // center position in prefix row (window base c0-8)

    // aligned in-bounds window base; edge blocks shift and fix up in smem
    const int wbase  = min(max(c0 - 8, 0), W_DIM - WIN);
    const int sh_fix = (c0 == 0) ? -8 : ((c0 + TW == W_DIM) ? 8 : 0);

    const uint32_t ring_u32 = (uint32_t)__cvta_generic_to_shared(ring);
    const uint32_t mbar_u32 = (uint32_t)__cvta_generic_to_shared(&mbar_sto);

    // ---- one TMA bulk copy: clamped row gr -> its ring slot (lane 0 only) ----
    auto issue_row = [&](int gr) {
        if (lane == 0) {
            const int grc = clampi(gr, 0, H_DIM - 1);
            const float* src = x + (size_t)grc * W_DIM + wbase;
            const uint32_t dst = ring_u32 + (uint32_t)((gr & (RING - 1)) * TWP * 4);
            asm volatile(
                "cp.async.bulk.shared::cluster.global.mbarrier::complete_tx::bytes "
                "[%0], [%1], %2, [%3];"
                :: "r"(dst), "l"(src), "r"(ROW_BYTES), "r"(mbar_u32) : "memory");
        }
    };

    // ---- border blocks: rewrite raw row so smem[m] = x[clamp(c0-8+m)] ----
    auto fixup_row = [&](int gr) {
        float* __restrict__ row = ring[gr & (RING - 1)];
        float v[9];
        #pragma unroll
        for (int i = 0; i < 9; i++) {
            const int col = lane + 32 * i;
            if (col < WIN) v[i] = row[clampi(col + sh_fix, 0, WIN - 1)];
        }
        __syncwarp();
        #pragma unroll
        for (int i = 0; i < 9; i++) {
            const int col = lane + 32 * i;
            if (col < WIN) row[col] = v[i];
        }
        __syncwarp();
    };

    // ---- warp-local in-place prefix scan: raw[0..271] -> P[0..272] ----
    auto scan_row = [&](int gr) {
        float* __restrict__ row = ring[gr & (RING - 1)];
        const int base = lane * 9;               // lanes 0..30 cover 0..271
        float ps[9];
        float tot = 0.0f;
        if (base < WIN) {
            float s = 0.0f;
            #pragma unroll
            for (int i = 0; i < 9; i++) {
                if (base + i < WIN) s += row[base + i];
                ps[i] = s;
            }
            tot = s;
        }
        float inc = tot;
        #pragma unroll
        for (int d = 1; d < 32; d <<= 1) {
            float n = __shfl_up_sync(0xffffffffu, inc, d);
            if (lane >= d) inc += n;
        }
        const float excl = inc - tot;
        __syncwarp();                            // raw reads done before overwrite
        if (lane == 0) row[0] = 0.0f;
        if (base < WIN) {
            #pragma unroll
            for (int i = 0; i < 9; i++)
                if (base + i < WIN) row[base + i + 1] = excl + ps[i];
        }
    };

    auto expect_tx = [&](uint32_t bytes) {
        asm volatile("mbarrier.arrive.expect_tx.shared::cta.b64 _, [%0], %1;"
                     :: "r"(mbar_u32), "r"(bytes) : "memory");
    };

    // ---- preload: rows r0-8..r0+7 (phase 0), then prefetch chunk 0 ----
    if (t == 0)
        asm volatile("mbarrier.init.shared::cta.b64 [%0], 1;" :: "r"(mbar_u32) : "memory");
    __syncthreads();
    if (t == 0) expect_tx(16 * ROW_BYTES);
    __syncthreads();                             // expect strictly before issues
    issue_row(r0 - 8 + wrp);
    issue_row(r0 + wrp);
    mbar_wait(mbar_u32, 0);
    if (t == 0) expect_tx(8 * ROW_BYTES);        // chunk 0 (phase 1); phase 0 done
    if (sh_fix) { fixup_row(r0 - 8 + wrp); fixup_row(r0 + wrp); }
    scan_row(r0 - 8 + wrp);
    scan_row(r0 + wrp);
    __syncthreads();
    issue_row(r0 + 8 + wrp);                     // chunk 0 raw rows in flight

    // ---- init vertical running sums: acc[ki] covers rows [r0-hk, r0+hk] ----
    float acc[7];
    #pragma unroll
    for (int ki = 0; ki < 7; ki++) {
        const int hk = ki + 1;                   // k = 2*hk+1
        float a = 0.0f;
        #pragma unroll
        for (int d = -7; d <= 7; d++) {
            if (d < -hk || d > hk) continue;
            const float* __restrict__ rp = &ring[(r0 + d) & (RING - 1)][j];
            a += rp[hk + 1] - rp[-hk];
        }
        acc[ki] = a;
    }

    // ---- main sweep: wait -> scan -> barrier -> issue next -> consume ----
    for (int c = 0; c < NCHUNK; c++) {
        const int prow = r0 + 8 + c * CHUNK;     // rows scanned this chunk
        mbar_wait(mbar_u32, (c + 1) & 1);        // chunk c completes phase c+1
        if (t == 0 && c + 1 < NCHUNK)
            expect_tx(8 * ROW_BYTES);            // next chunk (phase c+2)
        if (sh_fix) fixup_row(prow + wrp);
        scan_row(prow + wrp);
        __syncthreads();                         // prefixes visible to all
        if (c + 1 < NCHUNK)
            issue_row(prow + CHUNK + wrp);       // overlaps the consume below

        const int crow = r0 + c * CHUNK;
        size_t idx = (size_t)crow * W_DIM + (size_t)(c0 + t);

        #pragma unroll
        for (int rr = 0; rr < CHUNK; rr++) {
            const int r = crow + rr;

            float s = acc[0] * (1.0f / (7.0f *   9.0f));
            s = fmaf(acc[1], 1.0f / (7.0f *  25.0f), s);
            s = fmaf(acc[2], 1.0f / (7.0f *  49.0f), s);
            s = fmaf(acc[3], 1.0f / (7.0f *  81.0f), s);
            s = fmaf(acc[4], 1.0f / (7.0f * 121.0f), s);
            s = fmaf(acc[5], 1.0f / (7.0f * 169.0f), s);
            s = fmaf(acc[6], 1.0f / (7.0f * 225.0f), s);
            out[idx] = s * mask[idx];

            #pragma unroll
            for (int ki = 0; ki < 7; ki++) {
                const int hk = ki + 1;
                const float* __restrict__ ra = &ring[(r + 1 + hk) & (RING - 1)][j];
                const float* __restrict__ rs = &ring[(r - hk)     & (RING - 1)][j];
                acc[ki] += (ra[hk + 1] - ra[-hk]) - (rs[hk + 1] - rs[-hk]);
            }
            idx += W_DIM;
        }
        // next chunk's TMA writes target slots == rows (crow+16..crow+23)
        // ≡ (crow-16..crow-9) mod 32: disjoint from this chunk's read window
        // (crow-7..crow+15); prior-chunk readers were fenced by __syncthreads.
    }
}

extern "C" void kernel_launch(void* const* d_in, const int* in_sizes, int n_in,
                              void* d_out, int out_size)
{
    const float* x    = (const float*)d_in[0];
    const float* mask = (const float*)d_in[1];
    float* out        = (float*)d_out;

    dim3 grid(W_DIM / TW, H_DIM / SH);
    dim3 block(NTH);
    meanconv_kernel<<<grid, block>>>(x, mask, out);
}